// round 10
// baseline (speedup 1.0000x reference)
#include <cuda_runtime.h>

// NSbuilder: emit [L=256, H=512, W=512] float bitstream.
// out[t,h,w] = (thresh > r) where
//   ns_mask = t < new_ns_len[h,w]
//   r       = ns_mask ? rng[t] : rng[t - new_ns_len]
//   thresh  = ns_mask ? src_ns[h,w] : src_st[h,w]
//
// R1's inner body verbatim (wall-champion: LDS rng table with dummy zone,
// float mask, __stcs streaming stores), with ONE structural change: each
// thread owns TWO float4 pixel-groups (p4, p4+256) -> 2 independent STG.128
// per t (doubled store MLP) and grid halves to 512 CTAs = single wave.

#define HW    (512 * 512)
#define HW4   (HW / 4)        // 65536 float4 per t-plane
#define LBITS 256
#define TC    64              // t-values per block (gridDim.y = 4)

__global__ __launch_bounds__(256) void nsb_kernel(
    const float* __restrict__ src_ns,
    const float* __restrict__ src_st,
    const float* __restrict__ nlen,
    const float* __restrict__ rng,
    float4* __restrict__ out)
{
    // s[i] = rng[i - 256] for i in [256, 512); [0,256) is a dummy zone read
    // only when the value is discarded, so t - n + 256 never needs a clamp.
    __shared__ float s[512];
    int tid = threadIdx.x;
    s[tid]       = 0.0f;
    s[tid + 256] = rng[tid];
    __syncthreads();

    // Two float4 pixel-groups per thread: adjacent 4KB blocks.
    int pA = blockIdx.x * 512 + tid;        // [0, 65536), first block
    int pB = pA + 256;                      // second block

    float4 nsA = reinterpret_cast<const float4*>(src_ns)[pA];
    float4 stA = reinterpret_cast<const float4*>(src_st)[pA];
    float4 nlA = reinterpret_cast<const float4*>(nlen)[pA];
    float4 nsB = reinterpret_cast<const float4*>(src_ns)[pB];
    float4 stB = reinterpret_cast<const float4*>(src_st)[pB];
    float4 nlB = reinterpret_cast<const float4*>(nlen)[pB];

    // new_ns_len is integral-valued float.
    int a0 = (int)nlA.x, a1 = (int)nlA.y, a2 = (int)nlA.z, a3 = (int)nlA.w;
    int b0 = (int)nlB.x, b1 = (int)nlB.y, b2 = (int)nlB.z, b3 = (int)nlB.w;

    int tbase = blockIdx.y * TC;
    float4* optrA = out + (size_t)tbase * HW4 + (size_t)pA;
    float4* optrB = out + (size_t)tbase * HW4 + (size_t)pB;

    #pragma unroll 4
    for (int t = tbase; t < tbase + TC; ++t) {
        float rt = s[t + 256];              // rng[t], warp-uniform broadcast
        float tf = (float)t;
        float4 oA, oB;

        {
            bool  m  = tf < nlA.x;
            float r  = m ? rt    : s[t - a0 + 256];
            float th = m ? nsA.x : stA.x;
            oA.x = (th > r) ? 1.0f : 0.0f;
        }
        {
            bool  m  = tf < nlA.y;
            float r  = m ? rt    : s[t - a1 + 256];
            float th = m ? nsA.y : stA.y;
            oA.y = (th > r) ? 1.0f : 0.0f;
        }
        {
            bool  m  = tf < nlA.z;
            float r  = m ? rt    : s[t - a2 + 256];
            float th = m ? nsA.z : stA.z;
            oA.z = (th > r) ? 1.0f : 0.0f;
        }
        {
            bool  m  = tf < nlA.w;
            float r  = m ? rt    : s[t - a3 + 256];
            float th = m ? nsA.w : stA.w;
            oA.w = (th > r) ? 1.0f : 0.0f;
        }

        {
            bool  m  = tf < nlB.x;
            float r  = m ? rt    : s[t - b0 + 256];
            float th = m ? nsB.x : stB.x;
            oB.x = (th > r) ? 1.0f : 0.0f;
        }
        {
            bool  m  = tf < nlB.y;
            float r  = m ? rt    : s[t - b1 + 256];
            float th = m ? nsB.y : stB.y;
            oB.y = (th > r) ? 1.0f : 0.0f;
        }
        {
            bool  m  = tf < nlB.z;
            float r  = m ? rt    : s[t - b2 + 256];
            float th = m ? nsB.z : stB.z;
            oB.z = (th > r) ? 1.0f : 0.0f;
        }
        {
            bool  m  = tf < nlB.w;
            float r  = m ? rt    : s[t - b3 + 256];
            float th = m ? nsB.w : stB.w;
            oB.w = (th > r) ? 1.0f : 0.0f;
        }

        // Two independent streaming stores per iteration (doubled MLP).
        __stcs(optrA, oA);
        __stcs(optrB, oB);
        optrA += HW4;
        optrB += HW4;
    }
}

extern "C" void kernel_launch(void* const* d_in, const int* in_sizes, int n_in,
                              void* d_out, int out_size)
{
    const float* src_ns = (const float*)d_in[0];
    const float* src_st = (const float*)d_in[1];
    const float* nlen   = (const float*)d_in[2];
    const float* rng    = (const float*)d_in[3];
    float4* out = (float4*)d_out;

    dim3 grid(HW4 / 512, LBITS / TC);   // (128, 4) = 512 CTAs, single wave
    nsb_kernel<<<grid, 256>>>(src_ns, src_st, nlen, rng, out);
}

// round 12
// speedup vs baseline: 1.1456x; 1.1456x over previous
#include <cuda_runtime.h>

// NSbuilder: emit [L=256, H=512, W=512] float bitstream.
// out[t,h,w] = (thresh > r) where
//   ns_mask = t < new_ns_len[h,w]
//   r       = ns_mask ? rng[t] : rng[t - new_ns_len]
//   thresh  = ns_mask ? src_ns[h,w] : src_st[h,w]
//
// FINAL (session champion, reproduced twice at 43.5/43.8us wall).
// The kernel is a pure 268MB write stream; sustained wall throughput
// ~6.2TB/s is the effective HBM3e write ceiling. Falsified alternatives:
// register-computed van-der-Corput rng (__brev), TMA bulk stores (x2
// configs), write-through stores, single-wave reg squeeze, L2 evict_last
// residency pinning, 2-pixel-per-thread store MLP — all 2-6us slower.

#define HW   (512 * 512)
#define HW4  (HW / 4)
#define LBITS 256
#define TC    64          // t-values per block (gridDim.y = LBITS/TC)

__global__ __launch_bounds__(256) void nsb_kernel(
    const float* __restrict__ src_ns,
    const float* __restrict__ src_st,
    const float* __restrict__ nlen,
    const float* __restrict__ rng,
    float4* __restrict__ out)
{
    // s[i] = rng[i - 256] for i in [256, 512); i in [0,256) is a dummy zone
    // read only when the value is discarded (ns branch taken), so stable-index
    // t - nli + 256 is always in-bounds without a clamp.
    __shared__ float s[512];
    int tid = threadIdx.x;
    s[tid]       = 0.0f;
    s[tid + 256] = rng[tid];
    __syncthreads();

    int p4 = blockIdx.x * 256 + tid;   // float4 pixel-group index [0, 65536)

    float4 ns = reinterpret_cast<const float4*>(src_ns)[p4];
    float4 st = reinterpret_cast<const float4*>(src_st)[p4];
    float4 nl = reinterpret_cast<const float4*>(nlen)[p4];

    // new_ns_len is integral-valued float; (int) matches the reference's
    // astype(int32) on the (t - nl) clip path.
    int n0 = (int)nl.x, n1 = (int)nl.y, n2 = (int)nl.z, n3 = (int)nl.w;

    int tbase = blockIdx.y * TC;

    #pragma unroll 4
    for (int t = tbase; t < tbase + TC; ++t) {
        float rt = s[t + 256];         // rng[t], warp-uniform broadcast
        float tf = (float)t;
        float4 o;

        {
            bool  m  = tf < nl.x;                    // reference: t < new_ns_len (float)
            float r  = m ? rt   : s[t - n0 + 256];
            float th = m ? ns.x : st.x;
            o.x = (th > r) ? 1.0f : 0.0f;
        }
        {
            bool  m  = tf < nl.y;
            float r  = m ? rt   : s[t - n1 + 256];
            float th = m ? ns.y : st.y;
            o.y = (th > r) ? 1.0f : 0.0f;
        }
        {
            bool  m  = tf < nl.z;
            float r  = m ? rt   : s[t - n2 + 256];
            float th = m ? ns.z : st.z;
            o.z = (th > r) ? 1.0f : 0.0f;
        }
        {
            bool  m  = tf < nl.w;
            float r  = m ? rt   : s[t - n3 + 256];
            float th = m ? ns.w : st.w;
            o.w = (th > r) ? 1.0f : 0.0f;
        }

        // Streaming store: 256 MB with zero reuse — evict-first, keep L2 clean.
        __stcs(&out[(size_t)t * HW4 + (size_t)p4], o);
    }
}

extern "C" void kernel_launch(void* const* d_in, const int* in_sizes, int n_in,
                              void* d_out, int out_size)
{
    const float* src_ns = (const float*)d_in[0];
    const float* src_st = (const float*)d_in[1];
    const float* nlen   = (const float*)d_in[2];
    const float* rng    = (const float*)d_in[3];
    float4* out = (float4*)d_out;

    dim3 grid(HW4 / 256, LBITS / TC);   // (256, 4)
    nsb_kernel<<<grid, 256>>>(src_ns, src_st, nlen, rng, out);
}